// round 2
// baseline (speedup 1.0000x reference)
#include <cuda_runtime.h>
#include <math.h>

#define B_   8
#define PLEN 2048
#define QLEN 1024
#define HID  1024

// Scratch (allocation-free rule: __device__ globals)
__device__ float g_pkey[(size_t)B_ * PLEN * HID];   // 64 MB
__device__ float g_qkey[(size_t)B_ * QLEN * HID];   // 32 MB

#define BM 128
#define BN 128
#define BK 8
#define TM 8
#define TN 8

// ---------------------------------------------------------------------------
// NT GEMM: C[m,n] = act( sum_k A[m,k] * B[n,k] ), A:[M,K] rm, B:[N,K] rm.
// Batched via blockIdx.z with element strides sA/sB/sC.
// ---------------------------------------------------------------------------
template <bool RELU>
__global__ __launch_bounds__(256, 2) void gemm_nt(
    const float* __restrict__ A, const float* __restrict__ Bm,
    float* __restrict__ C, int M, int N, int K,
    size_t sA, size_t sB, size_t sC)
{
    A  += (size_t)blockIdx.z * sA;
    Bm += (size_t)blockIdx.z * sB;
    C  += (size_t)blockIdx.z * sC;

    __shared__ float As[BK][BM];
    __shared__ float Bs[BK][BN];

    const int tid = threadIdx.x;
    const int tx  = tid & 15;       // 0..15 -> N micro-tile
    const int ty  = tid >> 4;       // 0..15 -> M micro-tile
    const int lr  = tid >> 1;       // 0..127: row within tile for loads
    const int lc  = (tid & 1) * 4;  // 0 or 4: k-offset for float4 load

    const float* Ap = A  + (size_t)(blockIdx.y * BM + lr) * K + lc;
    const float* Bp = Bm + (size_t)(blockIdx.x * BN + lr) * K + lc;

    float acc[TM][TN] = {};

    for (int k0 = 0; k0 < K; k0 += BK) {
        float4 av = *(const float4*)(Ap + k0);
        float4 bv = *(const float4*)(Bp + k0);
        As[lc + 0][lr] = av.x; As[lc + 1][lr] = av.y;
        As[lc + 2][lr] = av.z; As[lc + 3][lr] = av.w;
        Bs[lc + 0][lr] = bv.x; Bs[lc + 1][lr] = bv.y;
        Bs[lc + 2][lr] = bv.z; Bs[lc + 3][lr] = bv.w;
        __syncthreads();

        #pragma unroll
        for (int kk = 0; kk < BK; kk++) {
            float ar[TM], br[TN];
            #pragma unroll
            for (int i = 0; i < TM; i++) ar[i] = As[kk][ty * TM + i];
            #pragma unroll
            for (int j = 0; j < TN; j++) br[j] = Bs[kk][tx * TN + j];
            #pragma unroll
            for (int i = 0; i < TM; i++)
                #pragma unroll
                for (int j = 0; j < TN; j++)
                    acc[i][j] = fmaf(ar[i], br[j], acc[i][j]);
        }
        __syncthreads();
    }

    #pragma unroll
    for (int i = 0; i < TM; i++) {
        size_t row = (size_t)blockIdx.y * BM + ty * TM + i;
        #pragma unroll
        for (int j = 0; j < TN; j++) {
            float v = acc[i][j];
            if (RELU) v = fmaxf(v, 0.0f);
            C[row * N + blockIdx.x * BN + tx * TN + j] = v;
        }
    }
}

// ---------------------------------------------------------------------------
// NN GEMM: C[m,n] = sum_k A[m,k] * B[k,n], A:[M,K] rm, B:[K,N] rm. Batched.
// ---------------------------------------------------------------------------
__global__ __launch_bounds__(256, 2) void gemm_nn(
    const float* __restrict__ A, const float* __restrict__ Bm,
    float* __restrict__ C, int M, int N, int K,
    size_t sA, size_t sB, size_t sC)
{
    A  += (size_t)blockIdx.z * sA;
    Bm += (size_t)blockIdx.z * sB;
    C  += (size_t)blockIdx.z * sC;

    __shared__ float As[BK][BM];
    __shared__ float Bs[BK][BN];

    const int tid = threadIdx.x;
    const int tx  = tid & 15;
    const int ty  = tid >> 4;

    // A tile load (transpose into As): same as NT
    const int alr = tid >> 1;
    const int alc = (tid & 1) * 4;
    const float* Ap = A + (size_t)(blockIdx.y * BM + alr) * K + alc;

    // B tile load (direct): rows of B are contiguous in N
    const int blr = tid >> 5;        // 0..7  : k within tile
    const int blc = (tid & 31) * 4;  // 0..124: n within tile
    const float* Bp = Bm + (size_t)blr * N + blockIdx.x * BN + blc;

    float acc[TM][TN] = {};

    for (int k0 = 0; k0 < K; k0 += BK) {
        float4 av = *(const float4*)(Ap + k0);
        As[alc + 0][alr] = av.x; As[alc + 1][alr] = av.y;
        As[alc + 2][alr] = av.z; As[alc + 3][alr] = av.w;
        float4 bv = *(const float4*)(Bp + (size_t)k0 * N);
        *(float4*)&Bs[blr][blc] = bv;
        __syncthreads();

        #pragma unroll
        for (int kk = 0; kk < BK; kk++) {
            float ar[TM], br[TN];
            #pragma unroll
            for (int i = 0; i < TM; i++) ar[i] = As[kk][ty * TM + i];
            #pragma unroll
            for (int j = 0; j < TN; j++) br[j] = Bs[kk][tx * TN + j];
            #pragma unroll
            for (int i = 0; i < TM; i++)
                #pragma unroll
                for (int j = 0; j < TN; j++)
                    acc[i][j] = fmaf(ar[i], br[j], acc[i][j]);
        }
        __syncthreads();
    }

    #pragma unroll
    for (int i = 0; i < TM; i++) {
        size_t row = (size_t)blockIdx.y * BM + ty * TM + i;
        #pragma unroll
        for (int j = 0; j < TN; j++)
            C[row * N + blockIdx.x * BN + tx * TN + j] = acc[i][j];
    }
}

// ---------------------------------------------------------------------------
// In-place row softmax over Q (=1024) with q_mask (True = pad -> -inf).
// One block of 256 threads per (b, p) row; 4 elements per thread.
// ---------------------------------------------------------------------------
__global__ __launch_bounds__(256) void softmax_rows(
    float* __restrict__ sc, const unsigned char* __restrict__ qmask)
{
    const int row = blockIdx.x;           // b * PLEN + p
    const int b   = row / PLEN;
    float* s = sc + (size_t)row * QLEN;
    const unsigned char* m = qmask + (size_t)b * QLEN;

    const int t = threadIdx.x;
    float v[4];
    float mx = -INFINITY;
    #pragma unroll
    for (int i = 0; i < 4; i++) {
        int idx = t + i * 256;
        float x = s[idx];
        if (m[idx]) x = -INFINITY;
        v[i] = x;
        mx = fmaxf(mx, x);
    }

    __shared__ float warpred[8];
    __shared__ float bcast;

    // block max
    #pragma unroll
    for (int o = 16; o; o >>= 1) mx = fmaxf(mx, __shfl_xor_sync(0xffffffffu, mx, o));
    if ((t & 31) == 0) warpred[t >> 5] = mx;
    __syncthreads();
    if (t == 0) {
        float r = warpred[0];
        #pragma unroll
        for (int w = 1; w < 8; w++) r = fmaxf(r, warpred[w]);
        bcast = r;
    }
    __syncthreads();
    mx = bcast;

    float sum = 0.0f;
    #pragma unroll
    for (int i = 0; i < 4; i++) {
        v[i] = expf(v[i] - mx);   // exp(-inf) = 0 for masked
        sum += v[i];
    }
    __syncthreads();  // warpred reuse guard

    #pragma unroll
    for (int o = 16; o; o >>= 1) sum += __shfl_xor_sync(0xffffffffu, sum, o);
    if ((t & 31) == 0) warpred[t >> 5] = sum;
    __syncthreads();
    if (t == 0) {
        float r = 0.0f;
        #pragma unroll
        for (int w = 0; w < 8; w++) r += warpred[w];
        bcast = r;
    }
    __syncthreads();
    const float inv = 1.0f / bcast;

    #pragma unroll
    for (int i = 0; i < 4; i++)
        s[t + i * 256] = v[i] * inv;
}

// ---------------------------------------------------------------------------
extern "C" void kernel_launch(void* const* d_in, const int* in_sizes, int n_in,
                              void* d_out, int out_size)
{
    const float*         k     = (const float*)d_in[0];          // [B, P, H]
    const float*         q     = (const float*)d_in[1];          // [B, Q, H]
    const unsigned char* qmask = (const unsigned char*)d_in[2];  // [B, Q] bool
    const float*         Wk    = (const float*)d_in[3];          // [H, H]
    const float*         Wq    = (const float*)d_in[4];          // [H, H]

    float* ctx    = (float*)d_out;                               // [B, P, H]
    float* alphas = ctx + (size_t)B_ * PLEN * HID;               // [B, P, Q]

    float *pkey, *qkey;
    cudaGetSymbolAddress((void**)&pkey, g_pkey);
    cudaGetSymbolAddress((void**)&qkey, g_qkey);

    dim3 blk(256);

    // 1) p_key = relu(k @ Wk^T)  : M=B*P=16384, N=H, K=H
    gemm_nt<true><<<dim3(HID / BN, (B_ * PLEN) / BM, 1), blk>>>(
        k, Wk, pkey, B_ * PLEN, HID, HID, 0, 0, 0);

    // 2) q_key = relu(q @ Wq^T)  : M=B*Q=8192
    gemm_nt<true><<<dim3(HID / BN, (B_ * QLEN) / BM, 1), blk>>>(
        q, Wq, qkey, B_ * QLEN, HID, HID, 0, 0, 0);

    // 3) scores[b] = p_key[b] @ q_key[b]^T  -> write raw into alphas region
    gemm_nt<false><<<dim3(QLEN / BN, PLEN / BM, B_), blk>>>(
        pkey, qkey, alphas, PLEN, QLEN, HID,
        (size_t)PLEN * HID, (size_t)QLEN * HID, (size_t)PLEN * QLEN);

    // 4) in-place softmax over Q per (b, p) row
    softmax_rows<<<B_ * PLEN, blk>>>(alphas, qmask);

    // 5) ctx[b] = alphas[b] @ q[b]
    gemm_nn<<<dim3(HID / BN, PLEN / BM, B_), blk>>>(
        alphas, q, ctx, PLEN, HID, QLEN,
        (size_t)PLEN * QLEN, (size_t)QLEN * HID, (size_t)PLEN * HID);
}

// round 4
// speedup vs baseline: 1.6112x; 1.6112x over previous
#include <cuda_runtime.h>
#include <cuda_bf16.h>
#include <math.h>
#include <stdint.h>

#define B_   8
#define PLEN 2048
#define QLEN 1024
#define HID  1024

// Scratch (__device__ globals: allocation-free rule)
__device__ float g_pkey[(size_t)B_ * PLEN * HID];   // 64 MB
__device__ float g_qkey[(size_t)B_ * QLEN * HID];   // 32 MB
__device__ float g_qT  [(size_t)B_ * HID  * QLEN];  // 32 MB

// ---------------------------------------------------------------------------
// helpers
// ---------------------------------------------------------------------------
__device__ __forceinline__ uint32_t smem_u32(const void* p) {
    return (uint32_t)__cvta_generic_to_shared(p);
}

// split two fp32 into packed bf16x2 (hi plane, lo plane); element0 in low half
__device__ __forceinline__ void split2(float x0, float x1,
                                       uint32_t& hi, uint32_t& lo) {
    __nv_bfloat16 h0 = __float2bfloat16_rn(x0);
    __nv_bfloat16 h1 = __float2bfloat16_rn(x1);
    float r0 = x0 - __bfloat162float(h0);
    float r1 = x1 - __bfloat162float(h1);
    __nv_bfloat16 l0 = __float2bfloat16_rn(r0);
    __nv_bfloat16 l1 = __float2bfloat16_rn(r1);
    hi = ((uint32_t)__bfloat16_as_ushort(h1) << 16) | __bfloat16_as_ushort(h0);
    lo = ((uint32_t)__bfloat16_as_ushort(l1) << 16) | __bfloat16_as_ushort(l0);
}

__device__ __forceinline__ void ldsm_x4(uint32_t r[4], uint32_t addr) {
    asm volatile("ldmatrix.sync.aligned.m8n8.x4.shared.b16 {%0,%1,%2,%3}, [%4];"
                 : "=r"(r[0]), "=r"(r[1]), "=r"(r[2]), "=r"(r[3]) : "r"(addr));
}

__device__ __forceinline__ void mma_bf16(float c[4], const uint32_t a[4],
                                         uint32_t b0, uint32_t b1) {
    asm volatile(
        "mma.sync.aligned.m16n8k16.row.col.f32.bf16.bf16.f32 "
        "{%0,%1,%2,%3}, {%4,%5,%6,%7}, {%8,%9}, {%0,%1,%2,%3};"
        : "+f"(c[0]), "+f"(c[1]), "+f"(c[2]), "+f"(c[3])
        : "r"(a[0]), "r"(a[1]), "r"(a[2]), "r"(a[3]), "r"(b0), "r"(b1));
}

// ---------------------------------------------------------------------------
// 3xBF16 NT GEMM: C[m,n] = (opt relu) sum_k A[m,k]*B[n,k], fp32 in/out.
// CTA tile 128x128, BK=32, double-buffered smem with split bf16 planes.
// 8 warps: 4(M) x 2(N); warp tile 32x64. lda=ldb=K. Batched via blockIdx.z.
// ---------------------------------------------------------------------------
#define STRD   80       // bytes per smem row: 32 bf16 (64B) + 16B pad
#define OFF_AH 0
#define OFF_AL 10240
#define OFF_BH 20480
#define OFF_BL 30720
#define STAGE  40960
#define GSMEM  (2 * STAGE)

__global__ __launch_bounds__(256) void gemm_3xbf16(
    const float* __restrict__ A, const float* __restrict__ Bm,
    float* __restrict__ C, int K, int ldc, int relu,
    size_t sA, size_t sB, size_t sC)
{
    extern __shared__ __align__(128) char smem[];
    const uint32_t sbase = smem_u32(smem);
    const int tid  = threadIdx.x;
    const int lane = tid & 31;
    const int wid  = tid >> 5;
    const int m0 = blockIdx.y * 128;
    const int n0 = blockIdx.x * 128;
    A  += (size_t)blockIdx.z * sA;
    Bm += (size_t)blockIdx.z * sB;
    C  += (size_t)blockIdx.z * sC;

    // producer indexing: 128 rows x 8 float4 per operand; 4 loads per thread
    uint32_t gofsA[4], gofsB[4], sts[4];
    #pragma unroll
    for (int i = 0; i < 4; i++) {
        int lin = tid + 256 * i;
        int row = lin >> 3, c4 = lin & 7;
        gofsA[i] = (uint32_t)((m0 + row) * K + c4 * 4) * 4u;
        gofsB[i] = (uint32_t)((n0 + row) * K + c4 * 4) * 4u;
        sts[i]   = (uint32_t)(row * STRD + c4 * 8);
    }

    uint2 rah[4], ral[4], rbh[4], rbl[4];
    const char* Ab = (const char*)A;
    const char* Bb = (const char*)Bm;

    auto LOAD = [&](int c) {
        uint32_t kb = (uint32_t)c * 128u;   // 32 floats
        #pragma unroll
        for (int i = 0; i < 4; i++) {
            float4 v = *(const float4*)(Ab + gofsA[i] + kb);
            split2(v.x, v.y, rah[i].x, ral[i].x);
            split2(v.z, v.w, rah[i].y, ral[i].y);
        }
        #pragma unroll
        for (int i = 0; i < 4; i++) {
            float4 v = *(const float4*)(Bb + gofsB[i] + kb);
            split2(v.x, v.y, rbh[i].x, rbl[i].x);
            split2(v.z, v.w, rbh[i].y, rbl[i].y);
        }
    };
    auto STORE = [&](int s) {
        char* st = smem + s * STAGE;
        #pragma unroll
        for (int i = 0; i < 4; i++) {
            *(uint2*)(st + OFF_AH + sts[i]) = rah[i];
            *(uint2*)(st + OFF_AL + sts[i]) = ral[i];
            *(uint2*)(st + OFF_BH + sts[i]) = rbh[i];
            *(uint2*)(st + OFF_BL + sts[i]) = rbl[i];
        }
    };

    // consumer indexing
    const int wm = (wid & 3) * 32;   // warp M offset in tile
    const int wn = (wid >> 2) * 64;  // warp N offset in tile
    // A ldmatrix lane address pieces
    const int a_row = (lane & 15);
    const int a_kc  = (lane >> 4) * 8;
    // B ldmatrix lane address pieces (x4 covers two n8 tiles)
    const int b_row = ((lane >> 4) << 3) + (lane & 7);
    const int b_kc  = ((lane >> 3) & 1) * 8;

    float acc[2][8][4] = {};

    const int nCh = K / 32;
    LOAD(0); STORE(0);
    __syncthreads();

    for (int c = 0; c < nCh; ++c) {
        const int s = c & 1;
        const bool more = (c + 1) < nCh;
        if (more) LOAD(c + 1);

        const uint32_t stb = sbase + s * STAGE;
        #pragma unroll
        for (int kk = 0; kk < 32; kk += 16) {
            uint32_t ah[2][4], al[2][4];
            #pragma unroll
            for (int mt = 0; mt < 2; mt++) {
                uint32_t ro = (uint32_t)((wm + mt * 16 + a_row) * STRD +
                                         (kk + a_kc) * 2);
                ldsm_x4(ah[mt], stb + OFF_AH + ro);
                ldsm_x4(al[mt], stb + OFF_AL + ro);
            }
            #pragma unroll
            for (int np = 0; np < 4; np++) {
                uint32_t ro = (uint32_t)((wn + np * 16 + b_row) * STRD +
                                         (kk + b_kc) * 2);
                uint32_t bh[4], bl[4];
                ldsm_x4(bh, stb + OFF_BH + ro);
                ldsm_x4(bl, stb + OFF_BL + ro);
                #pragma unroll
                for (int mt = 0; mt < 2; mt++) {
                    #pragma unroll
                    for (int nt = 0; nt < 2; nt++) {
                        float* cc = acc[mt][np * 2 + nt];
                        mma_bf16(cc, ah[mt], bh[nt * 2], bh[nt * 2 + 1]);
                        mma_bf16(cc, ah[mt], bl[nt * 2], bl[nt * 2 + 1]);
                        mma_bf16(cc, al[mt], bh[nt * 2], bh[nt * 2 + 1]);
                    }
                }
            }
        }
        __syncthreads();
        if (more) { STORE((c + 1) & 1); __syncthreads(); }
    }

    // epilogue
    const int g = lane >> 2, cc2 = (lane & 3) * 2;
    #pragma unroll
    for (int mt = 0; mt < 2; mt++) {
        #pragma unroll
        for (int j = 0; j < 8; j++) {
            int row = m0 + wm + mt * 16 + g;
            int col = n0 + wn + j * 8 + cc2;
            float* a4 = acc[mt][j];
            if (relu) {
                a4[0] = fmaxf(a4[0], 0.f); a4[1] = fmaxf(a4[1], 0.f);
                a4[2] = fmaxf(a4[2], 0.f); a4[3] = fmaxf(a4[3], 0.f);
            }
            *(float2*)(C + (size_t)row * ldc + col)       = make_float2(a4[0], a4[1]);
            *(float2*)(C + (size_t)(row + 8) * ldc + col) = make_float2(a4[2], a4[3]);
        }
    }
}

// ---------------------------------------------------------------------------
// q[b][j][h] -> qT[b][h][j]
// ---------------------------------------------------------------------------
__global__ void transpose_q(const float* __restrict__ q, float* __restrict__ qT)
{
    __shared__ float tile[32][33];
    const int b = blockIdx.z;
    const int j0 = blockIdx.x * 32, h0 = blockIdx.y * 32;
    const float* qb = q + (size_t)b * QLEN * HID;
    float* tb = qT + (size_t)b * HID * QLEN;
    #pragma unroll
    for (int r = threadIdx.y; r < 32; r += 8)
        tile[r][threadIdx.x] = qb[(size_t)(j0 + r) * HID + h0 + threadIdx.x];
    __syncthreads();
    #pragma unroll
    for (int r = threadIdx.y; r < 32; r += 8)
        tb[(size_t)(h0 + r) * QLEN + j0 + threadIdx.x] = tile[threadIdx.x][r];
}

// ---------------------------------------------------------------------------
// In-place row softmax over Q with q_mask (True = pad -> -inf).
// ---------------------------------------------------------------------------
__global__ __launch_bounds__(256) void softmax_rows(
    float* __restrict__ sc, const unsigned char* __restrict__ qmask)
{
    const int row = blockIdx.x;
    const int b   = row / PLEN;
    float* s = sc + (size_t)row * QLEN;
    const unsigned char* m = qmask + (size_t)b * QLEN;

    const int t = threadIdx.x;
    float v[4];
    float mx = -INFINITY;
    #pragma unroll
    for (int i = 0; i < 4; i++) {
        int idx = t + i * 256;
        float x = s[idx];
        if (m[idx]) x = -INFINITY;
        v[i] = x;
        mx = fmaxf(mx, x);
    }

    __shared__ float warpred[8];
    __shared__ float bcast;

    #pragma unroll
    for (int o = 16; o; o >>= 1) mx = fmaxf(mx, __shfl_xor_sync(0xffffffffu, mx, o));
    if ((t & 31) == 0) warpred[t >> 5] = mx;
    __syncthreads();
    if (t == 0) {
        float r = warpred[0];
        #pragma unroll
        for (int w = 1; w < 8; w++) r = fmaxf(r, warpred[w]);
        bcast = r;
    }
    __syncthreads();
    mx = bcast;

    float sum = 0.0f;
    #pragma unroll
    for (int i = 0; i < 4; i++) { v[i] = expf(v[i] - mx); sum += v[i]; }
    __syncthreads();

    #pragma unroll
    for (int o = 16; o; o >>= 1) sum += __shfl_xor_sync(0xffffffffu, sum, o);
    if ((t & 31) == 0) warpred[t >> 5] = sum;
    __syncthreads();
    if (t == 0) {
        float r = 0.0f;
        #pragma unroll
        for (int w = 0; w < 8; w++) r += warpred[w];
        bcast = r;
    }
    __syncthreads();
    const float inv = 1.0f / bcast;

    #pragma unroll
    for (int i = 0; i < 4; i++)
        s[t + i * 256] = v[i] * inv;
}

// ---------------------------------------------------------------------------
extern "C" void kernel_launch(void* const* d_in, const int* in_sizes, int n_in,
                              void* d_out, int out_size)
{
    (void)in_sizes; (void)n_in; (void)out_size;
    const float*         k     = (const float*)d_in[0];          // [B, P, H]
    const float*         q     = (const float*)d_in[1];          // [B, Q, H]
    const unsigned char* qmask = (const unsigned char*)d_in[2];  // [B, Q] bool
    const float*         Wk    = (const float*)d_in[3];          // [H, H]
    const float*         Wq    = (const float*)d_in[4];          // [H, H]

    float* ctx    = (float*)d_out;                               // [B, P, H]
    float* alphas = ctx + (size_t)B_ * PLEN * HID;               // [B, P, Q]

    float *pkey, *qkey, *qT;
    cudaGetSymbolAddress((void**)&pkey, g_pkey);
    cudaGetSymbolAddress((void**)&qkey, g_qkey);
    cudaGetSymbolAddress((void**)&qT,   g_qT);

    static int smem_set = 0;
    if (!smem_set) {
        cudaFuncSetAttribute(gemm_3xbf16,
                             cudaFuncAttributeMaxDynamicSharedMemorySize, GSMEM);
        smem_set = 1;
    }

    // 0) qT[b] = q[b]^T
    transpose_q<<<dim3(QLEN / 32, HID / 32, B_), dim3(32, 8)>>>(q, qT);

    // 1) p_key = relu(k @ Wk^T)
    gemm_3xbf16<<<dim3(HID / 128, (B_ * PLEN) / 128, 1), 256, GSMEM>>>(
        k, Wk, pkey, HID, HID, 1, 0, 0, 0);

    // 2) q_key = relu(q @ Wq^T)
    gemm_3xbf16<<<dim3(HID / 128, (B_ * QLEN) / 128, 1), 256, GSMEM>>>(
        q, Wq, qkey, HID, HID, 1, 0, 0, 0);

    // 3) scores[b] = p_key[b] @ q_key[b]^T  -> raw into alphas region
    gemm_3xbf16<<<dim3(QLEN / 128, PLEN / 128, B_), 256, GSMEM>>>(
        pkey, qkey, alphas, HID, QLEN, 0,
        (size_t)PLEN * HID, (size_t)QLEN * HID, (size_t)PLEN * QLEN);

    // 4) softmax in place
    softmax_rows<<<B_ * PLEN, 256>>>(alphas, qmask);

    // 5) ctx[b] = alphas[b] @ q[b] == alphas[b] @ (qT[b])^T  (NT)
    gemm_3xbf16<<<dim3(HID / 128, PLEN / 128, B_), 256, GSMEM>>>(
        alphas, qT, ctx, QLEN, HID, 0,
        (size_t)PLEN * QLEN, (size_t)HID * QLEN, (size_t)PLEN * HID);
}

// round 5
// speedup vs baseline: 1.8215x; 1.1305x over previous
#include <cuda_runtime.h>
#include <cuda_bf16.h>
#include <math.h>
#include <stdint.h>

#define B_   8
#define PLEN 2048
#define QLEN 1024
#define HID  1024

// Scratch (__device__ globals: allocation-free rule)
__device__ float g_pkey[(size_t)B_ * PLEN * HID];   // 64 MB
__device__ float g_qkey[(size_t)B_ * QLEN * HID];   // 32 MB
__device__ float g_qT  [(size_t)B_ * HID  * QLEN];  // 32 MB

// ---------------------------------------------------------------------------
// helpers
// ---------------------------------------------------------------------------
__device__ __forceinline__ uint32_t smem_u32(const void* p) {
    return (uint32_t)__cvta_generic_to_shared(p);
}

// split two fp32 into packed bf16x2 (hi plane, lo plane); element0 in low half
__device__ __forceinline__ void split2(float x0, float x1,
                                       uint32_t& hi, uint32_t& lo) {
    __nv_bfloat16 h0 = __float2bfloat16_rn(x0);
    __nv_bfloat16 h1 = __float2bfloat16_rn(x1);
    float r0 = x0 - __bfloat162float(h0);
    float r1 = x1 - __bfloat162float(h1);
    __nv_bfloat16 l0 = __float2bfloat16_rn(r0);
    __nv_bfloat16 l1 = __float2bfloat16_rn(r1);
    hi = ((uint32_t)__bfloat16_as_ushort(h1) << 16) | __bfloat16_as_ushort(h0);
    lo = ((uint32_t)__bfloat16_as_ushort(l1) << 16) | __bfloat16_as_ushort(l0);
}

__device__ __forceinline__ void ldsm_x4(uint32_t r[4], uint32_t addr) {
    asm volatile("ldmatrix.sync.aligned.m8n8.x4.shared.b16 {%0,%1,%2,%3}, [%4];"
                 : "=r"(r[0]), "=r"(r[1]), "=r"(r[2]), "=r"(r[3]) : "r"(addr));
}

__device__ __forceinline__ void mma_bf16(float c[4], const uint32_t a[4],
                                         uint32_t b0, uint32_t b1) {
    asm volatile(
        "mma.sync.aligned.m16n8k16.row.col.f32.bf16.bf16.f32 "
        "{%0,%1,%2,%3}, {%4,%5,%6,%7}, {%8,%9}, {%0,%1,%2,%3};"
        : "+f"(c[0]), "+f"(c[1]), "+f"(c[2]), "+f"(c[3])
        : "r"(a[0]), "r"(a[1]), "r"(a[2]), "r"(a[3]), "r"(b0), "r"(b1));
}

// ---------------------------------------------------------------------------
// 3xBF16 NT GEMM: C[m,n] = (opt relu) sum_k A[m,k]*B[n,k], fp32 in/out.
// CTA tile 128x128, BK=32, double-buffered split-bf16 smem planes.
// 16 warps: 4(M) x 4(N); warp tile 32x32. One barrier per chunk.
// lda = ldb = K. Batched via blockIdx.z.
// ---------------------------------------------------------------------------
#define STRD   80       // bytes per smem row: 32 bf16 (64B) + 16B pad
#define OFF_AH 0
#define OFF_AL 10240
#define OFF_BH 20480
#define OFF_BL 30720
#define STAGE  40960
#define GSMEM  (2 * STAGE)

__global__ __launch_bounds__(512, 1) void gemm_3xbf16(
    const float* __restrict__ A, const float* __restrict__ Bm,
    float* __restrict__ C, int K, int ldc, int relu,
    size_t sA, size_t sB, size_t sC)
{
    extern __shared__ __align__(128) char smem[];
    const uint32_t sbase = smem_u32(smem);
    const int tid  = threadIdx.x;
    const int lane = tid & 31;
    const int wid  = tid >> 5;
    const int m0 = blockIdx.y * 128;
    const int n0 = blockIdx.x * 128;
    A  += (size_t)blockIdx.z * sA;
    Bm += (size_t)blockIdx.z * sB;
    C  += (size_t)blockIdx.z * sC;

    // producer indexing: 128 rows x 8 float4 per operand; 2+2 loads per thread
    uint32_t gofsA[2], gofsB[2], stsAB[2];
    #pragma unroll
    for (int i = 0; i < 2; i++) {
        int lin = tid + 512 * i;
        int row = lin >> 3, c4 = lin & 7;
        gofsA[i] = (uint32_t)((m0 + row) * K + c4 * 4) * 4u;
        gofsB[i] = (uint32_t)((n0 + row) * K + c4 * 4) * 4u;
        stsAB[i] = (uint32_t)(row * STRD + c4 * 8);
    }

    uint2 rah[2], ral[2], rbh[2], rbl[2];
    const char* Ab = (const char*)A;
    const char* Bb = (const char*)Bm;

    auto LOAD = [&](int c) {
        uint32_t kb = (uint32_t)c * 128u;   // 32 floats
        #pragma unroll
        for (int i = 0; i < 2; i++) {
            float4 v = *(const float4*)(Ab + gofsA[i] + kb);
            split2(v.x, v.y, rah[i].x, ral[i].x);
            split2(v.z, v.w, rah[i].y, ral[i].y);
        }
        #pragma unroll
        for (int i = 0; i < 2; i++) {
            float4 v = *(const float4*)(Bb + gofsB[i] + kb);
            split2(v.x, v.y, rbh[i].x, rbl[i].x);
            split2(v.z, v.w, rbh[i].y, rbl[i].y);
        }
    };
    auto STORE = [&](int s) {
        char* st = smem + s * STAGE;
        #pragma unroll
        for (int i = 0; i < 2; i++) {
            *(uint2*)(st + OFF_AH + stsAB[i]) = rah[i];
            *(uint2*)(st + OFF_AL + stsAB[i]) = ral[i];
            *(uint2*)(st + OFF_BH + stsAB[i]) = rbh[i];
            *(uint2*)(st + OFF_BL + stsAB[i]) = rbl[i];
        }
    };

    // consumer indexing: warp grid 4(M) x 4(N), warp tile 32x32
    const int wm = (wid & 3) * 32;
    const int wn = (wid >> 2) * 32;
    const int a_row = (lane & 15);
    const int a_kc  = (lane >> 4) * 8;
    const int b_row = ((lane >> 4) << 3) + (lane & 7);
    const int b_kc  = ((lane >> 3) & 1) * 8;

    float acc[2][4][4] = {};   // [mt][np][frag]

    const int nCh = K / 32;
    LOAD(0); STORE(0);
    __syncthreads();

    #pragma unroll 1
    for (int c = 0; c < nCh; ++c) {
        const int s = c & 1;
        const bool more = (c + 1) < nCh;
        if (more) LOAD(c + 1);

        const uint32_t stb = sbase + s * STAGE;
        #pragma unroll
        for (int kk = 0; kk < 32; kk += 16) {
            uint32_t ah[2][4], al[2][4];
            #pragma unroll
            for (int mt = 0; mt < 2; mt++) {
                uint32_t ro = (uint32_t)((wm + mt * 16 + a_row) * STRD +
                                         (kk + a_kc) * 2);
                ldsm_x4(ah[mt], stb + OFF_AH + ro);
                ldsm_x4(al[mt], stb + OFF_AL + ro);
            }
            #pragma unroll
            for (int nb = 0; nb < 2; nb++) {
                uint32_t ro = (uint32_t)((wn + nb * 16 + b_row) * STRD +
                                         (kk + b_kc) * 2);
                uint32_t bh[4], bl[4];
                ldsm_x4(bh, stb + OFF_BH + ro);
                ldsm_x4(bl, stb + OFF_BL + ro);
                #pragma unroll
                for (int mt = 0; mt < 2; mt++) {
                    #pragma unroll
                    for (int nt = 0; nt < 2; nt++) {
                        float* cc = acc[mt][nb * 2 + nt];
                        mma_bf16(cc, ah[mt], bh[nt * 2], bh[nt * 2 + 1]);
                        mma_bf16(cc, ah[mt], bl[nt * 2], bl[nt * 2 + 1]);
                        mma_bf16(cc, al[mt], bh[nt * 2], bh[nt * 2 + 1]);
                    }
                }
            }
        }
        if (more) STORE((c + 1) & 1);   // that buffer was consumed at iter c-1
        __syncthreads();
    }

    // epilogue
    const int g = lane >> 2, cc2 = (lane & 3) * 2;
    #pragma unroll
    for (int mt = 0; mt < 2; mt++) {
        #pragma unroll
        for (int j = 0; j < 4; j++) {
            int row = m0 + wm + mt * 16 + g;
            int col = n0 + wn + j * 8 + cc2;
            float* a4 = acc[mt][j];
            if (relu) {
                a4[0] = fmaxf(a4[0], 0.f); a4[1] = fmaxf(a4[1], 0.f);
                a4[2] = fmaxf(a4[2], 0.f); a4[3] = fmaxf(a4[3], 0.f);
            }
            *(float2*)(C + (size_t)row * ldc + col)       = make_float2(a4[0], a4[1]);
            *(float2*)(C + (size_t)(row + 8) * ldc + col) = make_float2(a4[2], a4[3]);
        }
    }
}

// ---------------------------------------------------------------------------
// q[b][j][h] -> qT[b][h][j]
// ---------------------------------------------------------------------------
__global__ void transpose_q(const float* __restrict__ q, float* __restrict__ qT)
{
    __shared__ float tile[32][33];
    const int b = blockIdx.z;
    const int j0 = blockIdx.x * 32, h0 = blockIdx.y * 32;
    const float* qb = q + (size_t)b * QLEN * HID;
    float* tb = qT + (size_t)b * HID * QLEN;
    #pragma unroll
    for (int r = threadIdx.y; r < 32; r += 8)
        tile[r][threadIdx.x] = qb[(size_t)(j0 + r) * HID + h0 + threadIdx.x];
    __syncthreads();
    #pragma unroll
    for (int r = threadIdx.y; r < 32; r += 8)
        tb[(size_t)(h0 + r) * QLEN + j0 + threadIdx.x] = tile[threadIdx.x][r];
}

// ---------------------------------------------------------------------------
// In-place row softmax over Q with q_mask (True = pad -> -inf).
// ---------------------------------------------------------------------------
__global__ __launch_bounds__(256) void softmax_rows(
    float* __restrict__ sc, const unsigned char* __restrict__ qmask)
{
    const int row = blockIdx.x;
    const int b   = row / PLEN;
    float* s = sc + (size_t)row * QLEN;
    const unsigned char* m = qmask + (size_t)b * QLEN;

    const int t = threadIdx.x;
    float v[4];
    float mx = -INFINITY;
    #pragma unroll
    for (int i = 0; i < 4; i++) {
        int idx = t + i * 256;
        float x = s[idx];
        if (m[idx]) x = -INFINITY;
        v[i] = x;
        mx = fmaxf(mx, x);
    }

    __shared__ float warpred[8];
    __shared__ float bcast;

    #pragma unroll
    for (int o = 16; o; o >>= 1) mx = fmaxf(mx, __shfl_xor_sync(0xffffffffu, mx, o));
    if ((t & 31) == 0) warpred[t >> 5] = mx;
    __syncthreads();
    if (t == 0) {
        float r = warpred[0];
        #pragma unroll
        for (int w = 1; w < 8; w++) r = fmaxf(r, warpred[w]);
        bcast = r;
    }
    __syncthreads();
    mx = bcast;

    float sum = 0.0f;
    #pragma unroll
    for (int i = 0; i < 4; i++) { v[i] = expf(v[i] - mx); sum += v[i]; }
    __syncthreads();

    #pragma unroll
    for (int o = 16; o; o >>= 1) sum += __shfl_xor_sync(0xffffffffu, sum, o);
    if ((t & 31) == 0) warpred[t >> 5] = sum;
    __syncthreads();
    if (t == 0) {
        float r = 0.0f;
        #pragma unroll
        for (int w = 0; w < 8; w++) r += warpred[w];
        bcast = r;
    }
    __syncthreads();
    const float inv = 1.0f / bcast;

    #pragma unroll
    for (int i = 0; i < 4; i++)
        s[t + i * 256] = v[i] * inv;
}

// ---------------------------------------------------------------------------
extern "C" void kernel_launch(void* const* d_in, const int* in_sizes, int n_in,
                              void* d_out, int out_size)
{
    (void)in_sizes; (void)n_in; (void)out_size;
    const float*         k     = (const float*)d_in[0];          // [B, P, H]
    const float*         q     = (const float*)d_in[1];          // [B, Q, H]
    const unsigned char* qmask = (const unsigned char*)d_in[2];  // [B, Q] bool
    const float*         Wk    = (const float*)d_in[3];          // [H, H]
    const float*         Wq    = (const float*)d_in[4];          // [H, H]

    float* ctx    = (float*)d_out;                               // [B, P, H]
    float* alphas = ctx + (size_t)B_ * PLEN * HID;               // [B, P, Q]

    float *pkey, *qkey, *qT;
    cudaGetSymbolAddress((void**)&pkey, g_pkey);
    cudaGetSymbolAddress((void**)&qkey, g_qkey);
    cudaGetSymbolAddress((void**)&qT,   g_qT);

    static int smem_set = 0;
    if (!smem_set) {
        cudaFuncSetAttribute(gemm_3xbf16,
                             cudaFuncAttributeMaxDynamicSharedMemorySize, GSMEM);
        smem_set = 1;
    }

    // 0) qT[b] = q[b]^T
    transpose_q<<<dim3(QLEN / 32, HID / 32, B_), dim3(32, 8)>>>(q, qT);

    // 1) p_key = relu(k @ Wk^T)
    gemm_3xbf16<<<dim3(HID / 128, (B_ * PLEN) / 128, 1), 512, GSMEM>>>(
        k, Wk, pkey, HID, HID, 1, 0, 0, 0);

    // 2) q_key = relu(q @ Wq^T)
    gemm_3xbf16<<<dim3(HID / 128, (B_ * QLEN) / 128, 1), 512, GSMEM>>>(
        q, Wq, qkey, HID, HID, 1, 0, 0, 0);

    // 3) scores[b] = p_key[b] @ q_key[b]^T  -> raw into alphas region
    gemm_3xbf16<<<dim3(QLEN / 128, PLEN / 128, B_), 512, GSMEM>>>(
        pkey, qkey, alphas, HID, QLEN, 0,
        (size_t)PLEN * HID, (size_t)QLEN * HID, (size_t)PLEN * QLEN);

    // 4) softmax in place
    softmax_rows<<<B_ * PLEN, 256>>>(alphas, qmask);

    // 5) ctx[b] = alphas[b] @ q[b] == alphas[b] @ (qT[b])^T  (NT)
    gemm_3xbf16<<<dim3(HID / 128, PLEN / 128, B_), 512, GSMEM>>>(
        alphas, qT, ctx, QLEN, HID, 0,
        (size_t)PLEN * QLEN, (size_t)HID * QLEN, (size_t)PLEN * HID);
}

// round 6
// speedup vs baseline: 2.4207x; 1.3290x over previous
#include <cuda_runtime.h>
#include <cuda_bf16.h>
#include <math.h>
#include <stdint.h>

#define B_   8
#define PLEN 2048
#define QLEN 1024
#define HID  1024

// Scratch (__device__ globals: allocation-free rule)
__device__ float g_pkey[(size_t)B_ * PLEN * HID];   // 64 MB
__device__ float g_qkey[(size_t)B_ * QLEN * HID];   // 32 MB
__device__ float g_qT  [(size_t)B_ * HID  * QLEN];  // 32 MB

// ---------------------------------------------------------------------------
// helpers
// ---------------------------------------------------------------------------
__device__ __forceinline__ uint32_t smem_u32(const void* p) {
    return (uint32_t)__cvta_generic_to_shared(p);
}

// split two fp32 into packed bf16x2 (hi plane, lo plane); element0 in low half
__device__ __forceinline__ void split2(float x0, float x1,
                                       uint32_t& hi, uint32_t& lo) {
    __nv_bfloat16 h0 = __float2bfloat16_rn(x0);
    __nv_bfloat16 h1 = __float2bfloat16_rn(x1);
    float r0 = x0 - __bfloat162float(h0);
    float r1 = x1 - __bfloat162float(h1);
    __nv_bfloat16 l0 = __float2bfloat16_rn(r0);
    __nv_bfloat16 l1 = __float2bfloat16_rn(r1);
    hi = ((uint32_t)__bfloat16_as_ushort(h1) << 16) | __bfloat16_as_ushort(h0);
    lo = ((uint32_t)__bfloat16_as_ushort(l1) << 16) | __bfloat16_as_ushort(l0);
}

__device__ __forceinline__ void ldsm_x4(uint32_t r[4], uint32_t addr) {
    asm volatile("ldmatrix.sync.aligned.m8n8.x4.shared.b16 {%0,%1,%2,%3}, [%4];"
                 : "=r"(r[0]), "=r"(r[1]), "=r"(r[2]), "=r"(r[3]) : "r"(addr));
}

__device__ __forceinline__ void mma_bf16(float c[4], const uint32_t a[4],
                                         uint32_t b0, uint32_t b1) {
    asm volatile(
        "mma.sync.aligned.m16n8k16.row.col.f32.bf16.bf16.f32 "
        "{%0,%1,%2,%3}, {%4,%5,%6,%7}, {%8,%9}, {%0,%1,%2,%3};"
        : "+f"(c[0]), "+f"(c[1]), "+f"(c[2]), "+f"(c[3])
        : "r"(a[0]), "r"(a[1]), "r"(a[2]), "r"(a[3]), "r"(b0), "r"(b1));
}

// ---------------------------------------------------------------------------
// 3xBF16 NT GEMM: C[m,n] = (opt relu) sum_k A[m,k]*B[n,k], fp32 in/out.
// CTA tile 128x128, BK=32, double-buffered split-bf16 smem planes.
// 16 warps: 4(M) x 4(N); warp tile 32x32. One barrier per chunk.
// Inner loop issues three 8-MMA passes (hh, hl, lh) so consecutive MMAs hit
// distinct accumulators (RAW distance 8). Split/STS deferred past MMA block.
// ---------------------------------------------------------------------------
#define STRD   80       // bytes per smem row: 32 bf16 (64B) + 16B pad
#define OFF_AH 0
#define OFF_AL 10240
#define OFF_BH 20480
#define OFF_BL 30720
#define STAGE  40960
#define GSMEM  (2 * STAGE)

__global__ __launch_bounds__(512, 1) void gemm_3xbf16(
    const float* __restrict__ A, const float* __restrict__ Bm,
    float* __restrict__ C, int K, int ldc, int relu,
    size_t sA, size_t sB, size_t sC)
{
    extern __shared__ __align__(128) char smem[];
    const uint32_t sbase = smem_u32(smem);
    const int tid  = threadIdx.x;
    const int lane = tid & 31;
    const int wid  = tid >> 5;
    const int m0 = blockIdx.y * 128;
    const int n0 = blockIdx.x * 128;
    A  += (size_t)blockIdx.z * sA;
    Bm += (size_t)blockIdx.z * sB;
    C  += (size_t)blockIdx.z * sC;

    // producer indexing: 128 rows x 8 float4 per operand; 2+2 loads per thread
    uint32_t gofsA[2], gofsB[2], stsAB[2];
    #pragma unroll
    for (int i = 0; i < 2; i++) {
        int lin = tid + 512 * i;
        int row = lin >> 3, c4 = lin & 7;
        gofsA[i] = (uint32_t)((m0 + row) * K + c4 * 4) * 4u;
        gofsB[i] = (uint32_t)((n0 + row) * K + c4 * 4) * 4u;
        stsAB[i] = (uint32_t)(row * STRD + c4 * 8);
    }

    float4 va[2], vb[2];            // raw staged gmem data
    const char* Ab = (const char*)A;
    const char* Bb = (const char*)Bm;

    auto LOADRAW = [&](int c) {     // LDG only — no ALU in the MMA region
        uint32_t kb = (uint32_t)c * 128u;
        #pragma unroll
        for (int i = 0; i < 2; i++) va[i] = *(const float4*)(Ab + gofsA[i] + kb);
        #pragma unroll
        for (int i = 0; i < 2; i++) vb[i] = *(const float4*)(Bb + gofsB[i] + kb);
    };
    auto SPLITSTORE = [&](int s) {  // cvt/sub + STS, after the MMA block
        char* st = smem + s * STAGE;
        #pragma unroll
        for (int i = 0; i < 2; i++) {
            uint2 h, l;
            split2(va[i].x, va[i].y, h.x, l.x);
            split2(va[i].z, va[i].w, h.y, l.y);
            *(uint2*)(st + OFF_AH + stsAB[i]) = h;
            *(uint2*)(st + OFF_AL + stsAB[i]) = l;
        }
        #pragma unroll
        for (int i = 0; i < 2; i++) {
            uint2 h, l;
            split2(vb[i].x, vb[i].y, h.x, l.x);
            split2(vb[i].z, vb[i].w, h.y, l.y);
            *(uint2*)(st + OFF_BH + stsAB[i]) = h;
            *(uint2*)(st + OFF_BL + stsAB[i]) = l;
        }
    };

    // consumer indexing: warp grid 4(M) x 4(N), warp tile 32x32
    const int wm = (wid & 3) * 32;
    const int wn = (wid >> 2) * 32;
    const int a_row = (lane & 15);
    const int a_kc  = (lane >> 4) * 8;
    const int b_row = ((lane >> 4) << 3) + (lane & 7);
    const int b_kc  = ((lane >> 3) & 1) * 8;

    float acc[2][4][4] = {};   // [mt][nb*2+nt][frag]

    const int nCh = K / 32;
    LOADRAW(0); SPLITSTORE(0);
    __syncthreads();

    #pragma unroll 1
    for (int c = 0; c < nCh; ++c) {
        const int s = c & 1;
        const bool more = (c + 1) < nCh;
        if (more) LOADRAW(c + 1);   // LDGs in flight during MMAs

        const uint32_t stb = sbase + s * STAGE;
        #pragma unroll
        for (int kk = 0; kk < 32; kk += 16) {
            uint32_t ah[2][4], al[2][4], bh[2][4], bl[2][4];
            #pragma unroll
            for (int mt = 0; mt < 2; mt++) {
                uint32_t ro = (uint32_t)((wm + mt * 16 + a_row) * STRD +
                                         (kk + a_kc) * 2);
                ldsm_x4(ah[mt], stb + OFF_AH + ro);
                ldsm_x4(al[mt], stb + OFF_AL + ro);
            }
            #pragma unroll
            for (int nb = 0; nb < 2; nb++) {
                uint32_t ro = (uint32_t)((wn + nb * 16 + b_row) * STRD +
                                         (kk + b_kc) * 2);
                ldsm_x4(bh[nb], stb + OFF_BH + ro);
                ldsm_x4(bl[nb], stb + OFF_BL + ro);
            }
            // pass 1: hi*hi — 8 independent MMAs
            #pragma unroll
            for (int mt = 0; mt < 2; mt++)
                #pragma unroll
                for (int nb = 0; nb < 2; nb++)
                    #pragma unroll
                    for (int nt = 0; nt < 2; nt++)
                        mma_bf16(acc[mt][nb * 2 + nt], ah[mt],
                                 bh[nb][nt * 2], bh[nb][nt * 2 + 1]);
            // pass 2: hi*lo
            #pragma unroll
            for (int mt = 0; mt < 2; mt++)
                #pragma unroll
                for (int nb = 0; nb < 2; nb++)
                    #pragma unroll
                    for (int nt = 0; nt < 2; nt++)
                        mma_bf16(acc[mt][nb * 2 + nt], ah[mt],
                                 bl[nb][nt * 2], bl[nb][nt * 2 + 1]);
            // pass 3: lo*hi
            #pragma unroll
            for (int mt = 0; mt < 2; mt++)
                #pragma unroll
                for (int nb = 0; nb < 2; nb++)
                    #pragma unroll
                    for (int nt = 0; nt < 2; nt++)
                        mma_bf16(acc[mt][nb * 2 + nt], al[mt],
                                 bh[nb][nt * 2], bh[nb][nt * 2 + 1]);
        }
        if (more) SPLITSTORE((c + 1) & 1);  // buffer consumed at iter c-1
        __syncthreads();
    }

    // epilogue
    const int g = lane >> 2, cc2 = (lane & 3) * 2;
    #pragma unroll
    for (int mt = 0; mt < 2; mt++) {
        #pragma unroll
        for (int j = 0; j < 4; j++) {
            int row = m0 + wm + mt * 16 + g;
            int col = n0 + wn + j * 8 + cc2;
            float* a4 = acc[mt][j];
            if (relu) {
                a4[0] = fmaxf(a4[0], 0.f); a4[1] = fmaxf(a4[1], 0.f);
                a4[2] = fmaxf(a4[2], 0.f); a4[3] = fmaxf(a4[3], 0.f);
            }
            *(float2*)(C + (size_t)row * ldc + col)       = make_float2(a4[0], a4[1]);
            *(float2*)(C + (size_t)(row + 8) * ldc + col) = make_float2(a4[2], a4[3]);
        }
    }
}

// ---------------------------------------------------------------------------
// q[b][j][h] -> qT[b][h][j]
// ---------------------------------------------------------------------------
__global__ void transpose_q(const float* __restrict__ q, float* __restrict__ qT)
{
    __shared__ float tile[32][33];
    const int b = blockIdx.z;
    const int j0 = blockIdx.x * 32, h0 = blockIdx.y * 32;
    const float* qb = q + (size_t)b * QLEN * HID;
    float* tb = qT + (size_t)b * HID * QLEN;
    #pragma unroll
    for (int r = threadIdx.y; r < 32; r += 8)
        tile[r][threadIdx.x] = qb[(size_t)(j0 + r) * HID + h0 + threadIdx.x];
    __syncthreads();
    #pragma unroll
    for (int r = threadIdx.y; r < 32; r += 8)
        tb[(size_t)(h0 + r) * QLEN + j0 + threadIdx.x] = tile[threadIdx.x][r];
}

// ---------------------------------------------------------------------------
// In-place row softmax over Q with q_mask (True = pad -> -inf).
// ---------------------------------------------------------------------------
__global__ __launch_bounds__(256) void softmax_rows(
    float* __restrict__ sc, const unsigned char* __restrict__ qmask)
{
    const int row = blockIdx.x;
    const int b   = row / PLEN;
    float* s = sc + (size_t)row * QLEN;
    const unsigned char* m = qmask + (size_t)b * QLEN;

    const int t = threadIdx.x;
    float v[4];
    float mx = -INFINITY;
    #pragma unroll
    for (int i = 0; i < 4; i++) {
        int idx = t + i * 256;
        float x = s[idx];
        if (m[idx]) x = -INFINITY;
        v[i] = x;
        mx = fmaxf(mx, x);
    }

    __shared__ float warpred[8];
    __shared__ float bcast;

    #pragma unroll
    for (int o = 16; o; o >>= 1) mx = fmaxf(mx, __shfl_xor_sync(0xffffffffu, mx, o));
    if ((t & 31) == 0) warpred[t >> 5] = mx;
    __syncthreads();
    if (t == 0) {
        float r = warpred[0];
        #pragma unroll
        for (int w = 1; w < 8; w++) r = fmaxf(r, warpred[w]);
        bcast = r;
    }
    __syncthreads();
    mx = bcast;

    float sum = 0.0f;
    #pragma unroll
    for (int i = 0; i < 4; i++) { v[i] = expf(v[i] - mx); sum += v[i]; }
    __syncthreads();

    #pragma unroll
    for (int o = 16; o; o >>= 1) sum += __shfl_xor_sync(0xffffffffu, sum, o);
    if ((t & 31) == 0) warpred[t >> 5] = sum;
    __syncthreads();
    if (t == 0) {
        float r = 0.0f;
        #pragma unroll
        for (int w = 0; w < 8; w++) r += warpred[w];
        bcast = r;
    }
    __syncthreads();
    const float inv = 1.0f / bcast;

    #pragma unroll
    for (int i = 0; i < 4; i++)
        s[t + i * 256] = v[i] * inv;
}

// ---------------------------------------------------------------------------
extern "C" void kernel_launch(void* const* d_in, const int* in_sizes, int n_in,
                              void* d_out, int out_size)
{
    (void)in_sizes; (void)n_in; (void)out_size;
    const float*         k     = (const float*)d_in[0];          // [B, P, H]
    const float*         q     = (const float*)d_in[1];          // [B, Q, H]
    const unsigned char* qmask = (const unsigned char*)d_in[2];  // [B, Q] bool
    const float*         Wk    = (const float*)d_in[3];          // [H, H]
    const float*         Wq    = (const float*)d_in[4];          // [H, H]

    float* ctx    = (float*)d_out;                               // [B, P, H]
    float* alphas = ctx + (size_t)B_ * PLEN * HID;               // [B, P, Q]

    float *pkey, *qkey, *qT;
    cudaGetSymbolAddress((void**)&pkey, g_pkey);
    cudaGetSymbolAddress((void**)&qkey, g_qkey);
    cudaGetSymbolAddress((void**)&qT,   g_qT);

    static int smem_set = 0;
    if (!smem_set) {
        cudaFuncSetAttribute(gemm_3xbf16,
                             cudaFuncAttributeMaxDynamicSharedMemorySize, GSMEM);
        smem_set = 1;
    }

    // 0) qT[b] = q[b]^T
    transpose_q<<<dim3(QLEN / 32, HID / 32, B_), dim3(32, 8)>>>(q, qT);

    // 1) p_key = relu(k @ Wk^T)
    gemm_3xbf16<<<dim3(HID / 128, (B_ * PLEN) / 128, 1), 512, GSMEM>>>(
        k, Wk, pkey, HID, HID, 1, 0, 0, 0);

    // 2) q_key = relu(q @ Wq^T)
    gemm_3xbf16<<<dim3(HID / 128, (B_ * QLEN) / 128, 1), 512, GSMEM>>>(
        q, Wq, qkey, HID, HID, 1, 0, 0, 0);

    // 3) scores[b] = p_key[b] @ q_key[b]^T  -> raw into alphas region
    gemm_3xbf16<<<dim3(QLEN / 128, PLEN / 128, B_), 512, GSMEM>>>(
        pkey, qkey, alphas, HID, QLEN, 0,
        (size_t)PLEN * HID, (size_t)QLEN * HID, (size_t)PLEN * QLEN);

    // 4) softmax in place
    softmax_rows<<<B_ * PLEN, 256>>>(alphas, qmask);

    // 5) ctx[b] = alphas[b] @ q[b] == alphas[b] @ (qT[b])^T  (NT)
    gemm_3xbf16<<<dim3(HID / 128, PLEN / 128, B_), 512, GSMEM>>>(
        alphas, qT, ctx, QLEN, HID, 0,
        (size_t)PLEN * QLEN, (size_t)HID * QLEN, (size_t)PLEN * HID);
}

// round 7
// speedup vs baseline: 2.5759x; 1.0641x over previous
#include <cuda_runtime.h>
#include <cuda_bf16.h>
#include <math.h>
#include <stdint.h>

#define B_   8
#define PLEN 2048
#define QLEN 1024
#define HID  1024

// Scratch (__device__ globals: allocation-free rule)
__device__ float g_pkey[(size_t)B_ * PLEN * HID];   // 64 MB
__device__ float g_qkey[(size_t)B_ * QLEN * HID];   // 32 MB
__device__ float g_qT  [(size_t)B_ * HID  * QLEN];  // 32 MB

// ---------------------------------------------------------------------------
// helpers
// ---------------------------------------------------------------------------
__device__ __forceinline__ uint32_t smem_u32(const void* p) {
    return (uint32_t)__cvta_generic_to_shared(p);
}

// split two fp32 into packed bf16x2 (hi plane, lo plane); element0 in low half
__device__ __forceinline__ void split2(float x0, float x1,
                                       uint32_t& hi, uint32_t& lo) {
    __nv_bfloat16 h0 = __float2bfloat16_rn(x0);
    __nv_bfloat16 h1 = __float2bfloat16_rn(x1);
    float r0 = x0 - __bfloat162float(h0);
    float r1 = x1 - __bfloat162float(h1);
    __nv_bfloat16 l0 = __float2bfloat16_rn(r0);
    __nv_bfloat16 l1 = __float2bfloat16_rn(r1);
    hi = ((uint32_t)__bfloat16_as_ushort(h1) << 16) | __bfloat16_as_ushort(h0);
    lo = ((uint32_t)__bfloat16_as_ushort(l1) << 16) | __bfloat16_as_ushort(l0);
}

__device__ __forceinline__ void ldsm_x4(uint32_t r[4], uint32_t addr) {
    asm volatile("ldmatrix.sync.aligned.m8n8.x4.shared.b16 {%0,%1,%2,%3}, [%4];"
                 : "=r"(r[0]), "=r"(r[1]), "=r"(r[2]), "=r"(r[3]) : "r"(addr));
}

__device__ __forceinline__ void mma_bf16(float c[4], const uint32_t a[4],
                                         uint32_t b0, uint32_t b1) {
    asm volatile(
        "mma.sync.aligned.m16n8k16.row.col.f32.bf16.bf16.f32 "
        "{%0,%1,%2,%3}, {%4,%5,%6,%7}, {%8,%9}, {%0,%1,%2,%3};"
        : "+f"(c[0]), "+f"(c[1]), "+f"(c[2]), "+f"(c[3])
        : "r"(a[0]), "r"(a[1]), "r"(a[2]), "r"(a[3]), "r"(b0), "r"(b1));
}

// ---------------------------------------------------------------------------
// 3xBF16 NT GEMM: C[m,n] = (opt relu) sum_k A[m,k]*B[n,k], fp32 in/out.
// CTA tile 128x128, BK=64, double-buffered split-bf16 smem planes.
// 16 warps: 4(M) x 4(N); warp tile 32x32. One barrier per 64-K chunk.
// Three 8-MMA passes per k-step (hh, hl, lh) keep accumulator RAW distance 8.
// ---------------------------------------------------------------------------
#define STRD   144      // bytes per smem row: 64 bf16 (128B) + 16B pad
#define PLANE  18432    // 128 rows * 144
#define OFF_AH 0
#define OFF_AL PLANE
#define OFF_BH (2 * PLANE)
#define OFF_BL (3 * PLANE)
#define STAGE  (4 * PLANE)      // 73728
#define GSMEM  (2 * STAGE)      // 147456

__global__ __launch_bounds__(512, 1) void gemm_3xbf16(
    const float* __restrict__ A, const float* __restrict__ Bm,
    float* __restrict__ C, int K, int ldc, int relu,
    size_t sA, size_t sB, size_t sC)
{
    extern __shared__ __align__(128) char smem[];
    const uint32_t sbase = smem_u32(smem);
    const int tid  = threadIdx.x;
    const int lane = tid & 31;
    const int wid  = tid >> 5;
    const int m0 = blockIdx.y * 128;
    const int n0 = blockIdx.x * 128;
    A  += (size_t)blockIdx.z * sA;
    Bm += (size_t)blockIdx.z * sB;
    C  += (size_t)blockIdx.z * sC;

    // producer indexing: 128 rows x 16 float4 per operand; 4+4 loads/thread
    uint32_t gofsA[4], gofsB[4], stsAB[4];
    #pragma unroll
    for (int i = 0; i < 4; i++) {
        int lin = tid + 512 * i;
        int row = lin >> 4, c4 = lin & 15;
        gofsA[i] = (uint32_t)((m0 + row) * K + c4 * 4) * 4u;
        gofsB[i] = (uint32_t)((n0 + row) * K + c4 * 4) * 4u;
        stsAB[i] = (uint32_t)(row * STRD + c4 * 8);
    }

    float4 va[4], vb[4];            // raw staged gmem data
    const char* Ab = (const char*)A;
    const char* Bb = (const char*)Bm;

    auto LOADRAW = [&](int c) {     // LDG only — no ALU in the MMA region
        uint32_t kb = (uint32_t)c * 256u;   // 64 floats
        #pragma unroll
        for (int i = 0; i < 4; i++) va[i] = *(const float4*)(Ab + gofsA[i] + kb);
        #pragma unroll
        for (int i = 0; i < 4; i++) vb[i] = *(const float4*)(Bb + gofsB[i] + kb);
    };
    auto SPLITSTORE = [&](int s) {  // cvt/sub + STS, after the MMA block
        char* st = smem + s * STAGE;
        #pragma unroll
        for (int i = 0; i < 4; i++) {
            uint2 h, l;
            split2(va[i].x, va[i].y, h.x, l.x);
            split2(va[i].z, va[i].w, h.y, l.y);
            *(uint2*)(st + OFF_AH + stsAB[i]) = h;
            *(uint2*)(st + OFF_AL + stsAB[i]) = l;
        }
        #pragma unroll
        for (int i = 0; i < 4; i++) {
            uint2 h, l;
            split2(vb[i].x, vb[i].y, h.x, l.x);
            split2(vb[i].z, vb[i].w, h.y, l.y);
            *(uint2*)(st + OFF_BH + stsAB[i]) = h;
            *(uint2*)(st + OFF_BL + stsAB[i]) = l;
        }
    };

    // consumer indexing: warp grid 4(M) x 4(N), warp tile 32x32
    const int wm = (wid & 3) * 32;
    const int wn = (wid >> 2) * 32;
    const int a_row = (lane & 15);
    const int a_kc  = (lane >> 4) * 8;
    const int b_row = ((lane >> 4) << 3) + (lane & 7);
    const int b_kc  = ((lane >> 3) & 1) * 8;

    float acc[2][4][4] = {};   // [mt][nb*2+nt][frag]

    const int nCh = K / 64;
    LOADRAW(0); SPLITSTORE(0);
    __syncthreads();

    #pragma unroll 1
    for (int c = 0; c < nCh; ++c) {
        const int s = c & 1;
        const bool more = (c + 1) < nCh;
        if (more) LOADRAW(c + 1);   // LDGs in flight during MMAs

        const uint32_t stb = sbase + s * STAGE;
        #pragma unroll
        for (int kk = 0; kk < 64; kk += 16) {
            uint32_t ah[2][4], al[2][4], bh[2][4], bl[2][4];
            #pragma unroll
            for (int mt = 0; mt < 2; mt++) {
                uint32_t ro = (uint32_t)((wm + mt * 16 + a_row) * STRD +
                                         (kk + a_kc) * 2);
                ldsm_x4(ah[mt], stb + OFF_AH + ro);
                ldsm_x4(al[mt], stb + OFF_AL + ro);
            }
            #pragma unroll
            for (int nb = 0; nb < 2; nb++) {
                uint32_t ro = (uint32_t)((wn + nb * 16 + b_row) * STRD +
                                         (kk + b_kc) * 2);
                ldsm_x4(bh[nb], stb + OFF_BH + ro);
                ldsm_x4(bl[nb], stb + OFF_BL + ro);
            }
            // pass 1: hi*hi — 8 independent MMAs
            #pragma unroll
            for (int mt = 0; mt < 2; mt++)
                #pragma unroll
                for (int nb = 0; nb < 2; nb++)
                    #pragma unroll
                    for (int nt = 0; nt < 2; nt++)
                        mma_bf16(acc[mt][nb * 2 + nt], ah[mt],
                                 bh[nb][nt * 2], bh[nb][nt * 2 + 1]);
            // pass 2: hi*lo
            #pragma unroll
            for (int mt = 0; mt < 2; mt++)
                #pragma unroll
                for (int nb = 0; nb < 2; nb++)
                    #pragma unroll
                    for (int nt = 0; nt < 2; nt++)
                        mma_bf16(acc[mt][nb * 2 + nt], ah[mt],
                                 bl[nb][nt * 2], bl[nb][nt * 2 + 1]);
            // pass 3: lo*hi
            #pragma unroll
            for (int mt = 0; mt < 2; mt++)
                #pragma unroll
                for (int nb = 0; nb < 2; nb++)
                    #pragma unroll
                    for (int nt = 0; nt < 2; nt++)
                        mma_bf16(acc[mt][nb * 2 + nt], al[mt],
                                 bh[nb][nt * 2], bh[nb][nt * 2 + 1]);
        }
        if (more) SPLITSTORE((c + 1) & 1);  // buffer consumed at iter c-1
        __syncthreads();
    }

    // epilogue
    const int g = lane >> 2, cc2 = (lane & 3) * 2;
    #pragma unroll
    for (int mt = 0; mt < 2; mt++) {
        #pragma unroll
        for (int j = 0; j < 4; j++) {
            int row = m0 + wm + mt * 16 + g;
            int col = n0 + wn + j * 8 + cc2;
            float* a4 = acc[mt][j];
            if (relu) {
                a4[0] = fmaxf(a4[0], 0.f); a4[1] = fmaxf(a4[1], 0.f);
                a4[2] = fmaxf(a4[2], 0.f); a4[3] = fmaxf(a4[3], 0.f);
            }
            *(float2*)(C + (size_t)row * ldc + col)       = make_float2(a4[0], a4[1]);
            *(float2*)(C + (size_t)(row + 8) * ldc + col) = make_float2(a4[2], a4[3]);
        }
    }
}

// ---------------------------------------------------------------------------
// q[b][j][h] -> qT[b][h][j]
// ---------------------------------------------------------------------------
__global__ void transpose_q(const float* __restrict__ q, float* __restrict__ qT)
{
    __shared__ float tile[32][33];
    const int b = blockIdx.z;
    const int j0 = blockIdx.x * 32, h0 = blockIdx.y * 32;
    const float* qb = q + (size_t)b * QLEN * HID;
    float* tb = qT + (size_t)b * HID * QLEN;
    #pragma unroll
    for (int r = threadIdx.y; r < 32; r += 8)
        tile[r][threadIdx.x] = qb[(size_t)(j0 + r) * HID + h0 + threadIdx.x];
    __syncthreads();
    #pragma unroll
    for (int r = threadIdx.y; r < 32; r += 8)
        tb[(size_t)(h0 + r) * QLEN + j0 + threadIdx.x] = tile[threadIdx.x][r];
}

// ---------------------------------------------------------------------------
// In-place row softmax over Q with q_mask (True = pad -> -inf).
// ---------------------------------------------------------------------------
__global__ __launch_bounds__(256) void softmax_rows(
    float* __restrict__ sc, const unsigned char* __restrict__ qmask)
{
    const int row = blockIdx.x;
    const int b   = row / PLEN;
    float* s = sc + (size_t)row * QLEN;
    const unsigned char* m = qmask + (size_t)b * QLEN;

    const int t = threadIdx.x;
    float v[4];
    float mx = -INFINITY;
    #pragma unroll
    for (int i = 0; i < 4; i++) {
        int idx = t + i * 256;
        float x = s[idx];
        if (m[idx]) x = -INFINITY;
        v[i] = x;
        mx = fmaxf(mx, x);
    }

    __shared__ float warpred[8];
    __shared__ float bcast;

    #pragma unroll
    for (int o = 16; o; o >>= 1) mx = fmaxf(mx, __shfl_xor_sync(0xffffffffu, mx, o));
    if ((t & 31) == 0) warpred[t >> 5] = mx;
    __syncthreads();
    if (t == 0) {
        float r = warpred[0];
        #pragma unroll
        for (int w = 1; w < 8; w++) r = fmaxf(r, warpred[w]);
        bcast = r;
    }
    __syncthreads();
    mx = bcast;

    float sum = 0.0f;
    #pragma unroll
    for (int i = 0; i < 4; i++) { v[i] = expf(v[i] - mx); sum += v[i]; }
    __syncthreads();

    #pragma unroll
    for (int o = 16; o; o >>= 1) sum += __shfl_xor_sync(0xffffffffu, sum, o);
    if ((t & 31) == 0) warpred[t >> 5] = sum;
    __syncthreads();
    if (t == 0) {
        float r = 0.0f;
        #pragma unroll
        for (int w = 0; w < 8; w++) r += warpred[w];
        bcast = r;
    }
    __syncthreads();
    const float inv = 1.0f / bcast;

    #pragma unroll
    for (int i = 0; i < 4; i++)
        s[t + i * 256] = v[i] * inv;
}

// ---------------------------------------------------------------------------
extern "C" void kernel_launch(void* const* d_in, const int* in_sizes, int n_in,
                              void* d_out, int out_size)
{
    (void)in_sizes; (void)n_in; (void)out_size;
    const float*         k     = (const float*)d_in[0];          // [B, P, H]
    const float*         q     = (const float*)d_in[1];          // [B, Q, H]
    const unsigned char* qmask = (const unsigned char*)d_in[2];  // [B, Q] bool
    const float*         Wk    = (const float*)d_in[3];          // [H, H]
    const float*         Wq    = (const float*)d_in[4];          // [H, H]

    float* ctx    = (float*)d_out;                               // [B, P, H]
    float* alphas = ctx + (size_t)B_ * PLEN * HID;               // [B, P, Q]

    float *pkey, *qkey, *qT;
    cudaGetSymbolAddress((void**)&pkey, g_pkey);
    cudaGetSymbolAddress((void**)&qkey, g_qkey);
    cudaGetSymbolAddress((void**)&qT,   g_qT);

    static int smem_set = 0;
    if (!smem_set) {
        cudaFuncSetAttribute(gemm_3xbf16,
                             cudaFuncAttributeMaxDynamicSharedMemorySize, GSMEM);
        smem_set = 1;
    }

    // 0) qT[b] = q[b]^T
    transpose_q<<<dim3(QLEN / 32, HID / 32, B_), dim3(32, 8)>>>(q, qT);

    // 1) p_key = relu(k @ Wk^T)
    gemm_3xbf16<<<dim3(HID / 128, (B_ * PLEN) / 128, 1), 512, GSMEM>>>(
        k, Wk, pkey, HID, HID, 1, 0, 0, 0);

    // 2) q_key = relu(q @ Wq^T)
    gemm_3xbf16<<<dim3(HID / 128, (B_ * QLEN) / 128, 1), 512, GSMEM>>>(
        q, Wq, qkey, HID, HID, 1, 0, 0, 0);

    // 3) scores[b] = p_key[b] @ q_key[b]^T  -> raw into alphas region
    gemm_3xbf16<<<dim3(QLEN / 128, PLEN / 128, B_), 512, GSMEM>>>(
        pkey, qkey, alphas, HID, QLEN, 0,
        (size_t)PLEN * HID, (size_t)QLEN * HID, (size_t)PLEN * QLEN);

    // 4) softmax in place
    softmax_rows<<<B_ * PLEN, 256>>>(alphas, qmask);

    // 5) ctx[b] = alphas[b] @ q[b] == alphas[b] @ (qT[b])^T  (NT)
    gemm_3xbf16<<<dim3(HID / 128, PLEN / 128, B_), 512, GSMEM>>>(
        alphas, qT, ctx, QLEN, HID, 0,
        (size_t)PLEN * QLEN, (size_t)HID * QLEN, (size_t)PLEN * HID);
}